// round 1
// baseline (speedup 1.0000x reference)
#include <cuda_runtime.h>

// Problem dims (fixed by setup_inputs; N == T == 256 always)
#define B_    256
#define T_    256
#define DIN   512
#define DHID  512
#define DOUT  512
#define NCOMB 1024   // DHID + DOUT fused output columns
#define KDIM  512    // K for both x-part and h-part GEMMs

// Scratch: __device__ globals (allocation inside kernel_launch is forbidden)
__device__ float g_Wx[KDIM * NCOMB];              // rows   0..511 of [W_h | W_o]
__device__ float g_Wc[KDIM * NCOMB];              // rows 512..1023 of [W_h | W_o]
__device__ float g_bias[NCOMB];                   // [b_h | b_o]
__device__ float g_pre[T_ * B_ * NCOMB];          // [T][B][1024] = 268 MB, pre = xW + b
__device__ float g_h[2][B_ * DHID];               // double-buffered hidden state

// ---------------------------------------------------------------------------
// Prep: pack weights into fused [512 x 1024] matrices, bias, init h0.
// ---------------------------------------------------------------------------
__global__ void prep_kernel(const float* __restrict__ Wh, const float* __restrict__ bh,
                            const float* __restrict__ Wo, const float* __restrict__ bo,
                            const float* __restrict__ h0) {
    int i = blockIdx.x * blockDim.x + threadIdx.x;
    if (i < KDIM * NCOMB) {
        int k = i >> 10;          // / 1024
        int j = i & 1023;
        float vx, vc;
        if (j < DHID) {
            vx = Wh[k * DHID + j];
            vc = Wh[(k + DIN) * DHID + j];
        } else {
            int jj = j - DHID;
            vx = Wo[k * DOUT + jj];
            vc = Wo[(k + DIN) * DOUT + jj];
        }
        g_Wx[i] = vx;
        g_Wc[i] = vc;
    }
    if (i < NCOMB)      g_bias[i] = (i < DHID) ? bh[i] : bo[i - DHID];
    if (i < B_ * DHID)  g_h[0][i] = h0[i];
}

// ---------------------------------------------------------------------------
// Precompute GEMM: g_pre[m][n] = x_row(m) . g_Wx[:,n] + bias[n]
//   m = t*B + b  (so each t is a contiguous [B,1024] slab for the step kernel)
//   M = 65536, N = 1024, K = 512
// Tile: 128x64x16, 256 threads, 8x4 microtile.
// ---------------------------------------------------------------------------
#define PM 128
#define PN 64
#define PK 16
#define PMP (PM + 4)

__global__ __launch_bounds__(256) void pre_gemm_kernel(const float* __restrict__ x) {
    __shared__ float As[PK][PMP];   // A stored transposed [k][m]
    __shared__ float Bs[PK][PN];

    const int bn  = blockIdx.x * PN;
    const int bm  = blockIdx.y * PM;
    const int tid = threadIdx.x;
    const int tx  = tid & 15;       // 0..15 -> 4 output cols
    const int ty  = tid >> 4;       // 0..15 -> 8 output rows

    // A-tile load mapping: 2048 floats / 256 thr = 2 x float4 per thread
    const int arow = tid >> 2;          // 0..63
    const int acol = (tid & 3) * 4;     // 0,4,8,12
    // B-tile load mapping: 1024 floats / 256 thr = 1 x float4
    const int brow = tid >> 4;          // 0..15
    const int bcol = (tid & 15) * 4;

    // m = t*256 + b  ->  b = m & 255, t = m >> 8 ; x index = (b*T + t)*DIN
    const int m0 = bm + arow;
    const int m1 = m0 + 64;
    const float* a0 = x + (((m0 & 255) << 8) + (m0 >> 8)) * DIN;
    const float* a1 = x + (((m1 & 255) << 8) + (m1 >> 8)) * DIN;

    float acc[8][4];
#pragma unroll
    for (int i = 0; i < 8; i++)
#pragma unroll
        for (int j = 0; j < 4; j++) acc[i][j] = 0.f;

    for (int k0 = 0; k0 < KDIM; k0 += PK) {
        float4 va0 = *(const float4*)(a0 + k0 + acol);
        float4 va1 = *(const float4*)(a1 + k0 + acol);
        float4 vb  = *(const float4*)(g_Wx + (k0 + brow) * NCOMB + bn + bcol);
        As[acol + 0][arow] = va0.x; As[acol + 1][arow] = va0.y;
        As[acol + 2][arow] = va0.z; As[acol + 3][arow] = va0.w;
        As[acol + 0][arow + 64] = va1.x; As[acol + 1][arow + 64] = va1.y;
        As[acol + 2][arow + 64] = va1.z; As[acol + 3][arow + 64] = va1.w;
        *(float4*)(&Bs[brow][bcol]) = vb;
        __syncthreads();

#pragma unroll
        for (int kk = 0; kk < PK; kk++) {
            float a[8], b[4];
#pragma unroll
            for (int i = 0; i < 8; i++) a[i] = As[kk][ty * 8 + i];
#pragma unroll
            for (int j = 0; j < 4; j++) b[j] = Bs[kk][tx * 4 + j];
#pragma unroll
            for (int i = 0; i < 8; i++)
#pragma unroll
                for (int j = 0; j < 4; j++) acc[i][j] += a[i] * b[j];
        }
        __syncthreads();
    }

#pragma unroll
    for (int i = 0; i < 8; i++) {
        int m = bm + ty * 8 + i;
        int n = bn + tx * 4;
        float4 bias = *(const float4*)(g_bias + n);
        float4 v;
        v.x = acc[i][0] + bias.x;
        v.y = acc[i][1] + bias.y;
        v.z = acc[i][2] + bias.z;
        v.w = acc[i][3] + bias.w;
        *(float4*)(g_pre + m * NCOMB + n) = v;
    }
}

// ---------------------------------------------------------------------------
// Per-step GEMM: C = h_cur @ g_Wc + g_pre[t]; left half -> h_next,
// right half -> sigmoid -> out[b][t][:]. M=256, N=1024, K=512.
// Tile: 32x64x16, 256 threads, 2x4 microtile, 128 CTAs.
// ---------------------------------------------------------------------------
#define SM_ 32
#define SN_ 64
#define SK_ 16
#define SMP (SM_ + 4)

__global__ __launch_bounds__(256) void step_kernel(float* __restrict__ out, int t, int par) {
    __shared__ float As[SK_][SMP];
    __shared__ float Bs[SK_][SN_];

    const float* __restrict__ hcur  = g_h[par];
    float* __restrict__       hnext = g_h[par ^ 1];

    const int bn  = blockIdx.x * SN_;
    const int bm  = blockIdx.y * SM_;
    const int tid = threadIdx.x;
    const int tx  = tid & 15;       // 4 cols
    const int ty  = tid >> 4;       // 2 rows

    const int arow = tid >> 3;          // 0..31
    const int acol = (tid & 7) * 2;     // 0..14
    const int brow = tid >> 4;          // 0..15
    const int bcol = (tid & 15) * 4;

    float acc[2][4] = {{0.f, 0.f, 0.f, 0.f}, {0.f, 0.f, 0.f, 0.f}};

    for (int k0 = 0; k0 < KDIM; k0 += SK_) {
        float2 va = *(const float2*)(hcur + (bm + arow) * DHID + k0 + acol);
        float4 vb = *(const float4*)(g_Wc + (k0 + brow) * NCOMB + bn + bcol);
        As[acol + 0][arow] = va.x;
        As[acol + 1][arow] = va.y;
        *(float4*)(&Bs[brow][bcol]) = vb;
        __syncthreads();

#pragma unroll
        for (int kk = 0; kk < SK_; kk++) {
            float a0 = As[kk][ty * 2 + 0];
            float a1 = As[kk][ty * 2 + 1];
            float b0 = Bs[kk][tx * 4 + 0];
            float b1 = Bs[kk][tx * 4 + 1];
            float b2 = Bs[kk][tx * 4 + 2];
            float b3 = Bs[kk][tx * 4 + 3];
            acc[0][0] += a0 * b0; acc[0][1] += a0 * b1;
            acc[0][2] += a0 * b2; acc[0][3] += a0 * b3;
            acc[1][0] += a1 * b0; acc[1][1] += a1 * b1;
            acc[1][2] += a1 * b2; acc[1][3] += a1 * b3;
        }
        __syncthreads();
    }

#pragma unroll
    for (int i = 0; i < 2; i++) {
        int m = bm + ty * 2 + i;
        int n = bn + tx * 4;
        float4 pre = *(const float4*)(g_pre + (t * B_ + m) * NCOMB + n);
        float v0 = acc[i][0] + pre.x;
        float v1 = acc[i][1] + pre.y;
        float v2 = acc[i][2] + pre.z;
        float v3 = acc[i][3] + pre.w;
        if (bn < DHID) {                       // uniform per block (SN_ divides DHID)
            float4 v = {v0, v1, v2, v3};
            *(float4*)(hnext + m * DHID + n) = v;
        } else {
            float4 v;
            v.x = 1.f / (1.f + __expf(-v0));
            v.y = 1.f / (1.f + __expf(-v1));
            v.z = 1.f / (1.f + __expf(-v2));
            v.w = 1.f / (1.f + __expf(-v3));
            *(float4*)(out + ((size_t)m * T_ + t) * DOUT + (n - DHID)) = v;
        }
    }
}

// ---------------------------------------------------------------------------
// Final hidden state -> tail of d_out
// ---------------------------------------------------------------------------
__global__ void final_kernel(float* __restrict__ out) {
    int i = blockIdx.x * blockDim.x + threadIdx.x;
    if (i < B_ * DHID) out[(size_t)B_ * T_ * DOUT + i] = g_h[0][i];
}

// ---------------------------------------------------------------------------
// Launch: prep -> big parallel x-GEMM -> 256 sequential step GEMMs -> tail.
// All on the default stream; graph-capturable (kernel launches only).
// ---------------------------------------------------------------------------
extern "C" void kernel_launch(void* const* d_in, const int* in_sizes, int n_in,
                              void* d_out, int out_size) {
    const float* x  = (const float*)d_in[0];
    const float* h0 = (const float*)d_in[1];
    const float* Wh = (const float*)d_in[2];
    const float* bh = (const float*)d_in[3];
    const float* Wo = (const float*)d_in[4];
    const float* bo = (const float*)d_in[5];
    float* out = (float*)d_out;

    prep_kernel<<<(KDIM * NCOMB + 255) / 256, 256>>>(Wh, bh, Wo, bo, h0);

    pre_gemm_kernel<<<dim3(NCOMB / PN, (B_ * T_) / PM), 256>>>(x);

    for (int t = 0; t < T_; t++) {
        step_kernel<<<dim3(NCOMB / SN_, B_ / SM_), 256>>>(out, t, t & 1);
    }

    final_kernel<<<(B_ * DHID + 255) / 256, 256>>>(out);
}

// round 4
// speedup vs baseline: 2.8825x; 2.8825x over previous
#include <cuda_runtime.h>
#include <cstdint>

#define B_ 256
#define T_ 256

// ---------------- device-global scratch ----------------
__device__ float g_W1t[512 * 512];     // W_hx^T [n][k] tf32
__device__ float g_Wht[512 * 512];     // W_hh^T [n][k] tf32
__device__ float g_Whh[512 * 512];     // W_hh   [k][n] fp32
__device__ float g_W2[512 * 512];      // W_hh^2 fp32
__device__ float g_W4[512 * 512];      // W_hh^4 fp32
__device__ float g_Wot[512 * 1024];    // W_o^T  [n][k] tf32
__device__ float g_bh[512];
__device__ float g_bo[512];
__device__ float g_preh[65536 * 512];          // [t*256+b][n]
__device__ float g_Hall[(size_t)257 * 256 * 512]; // [t][b][n], t=0..256
__device__ float g_Q0[16384 * 512];
__device__ float g_Q1[16384 * 512];

// ---------------- helpers ----------------
__device__ __forceinline__ uint32_t smem_u32(const void* p) {
    uint32_t a;
    asm("{ .reg .u64 t; cvta.to.shared.u64 t, %1; cvt.u32.u64 %0, t; }" : "=r"(a) : "l"(p));
    return a;
}
__device__ __forceinline__ float rna_tf32(float x) {
    uint32_t r; asm("cvt.rna.tf32.f32 %0, %1;" : "=r"(r) : "f"(x));
    return __uint_as_float(r);
}
__device__ __forceinline__ uint32_t rna_u(float x) {
    uint32_t r; asm("cvt.rna.tf32.f32 %0, %1;" : "=r"(r) : "f"(x));
    return r;
}
// row maps: 0=identity, 1=(b,t)<->(t,b) gather, 2=chunk rows t=4k+off (m=(k<<8)|b)
__device__ __forceinline__ int rowmap(int mode, int off, int m) {
    if (mode == 1) return ((m & 255) << 8) | (m >> 8);
    if (mode == 2) return (((m >> 8) << 10) | (off << 8)) | (m & 255);
    return m;
}
__device__ __forceinline__ void mma8(float* c, const uint32_t* a, const uint32_t* b) {
    asm volatile("mma.sync.aligned.m16n8k8.row.col.f32.tf32.tf32.f32 "
        "{%0,%1,%2,%3}, {%4,%5,%6,%7}, {%8,%9}, {%0,%1,%2,%3};"
        : "+f"(c[0]), "+f"(c[1]), "+f"(c[2]), "+f"(c[3])
        : "r"(a[0]), "r"(a[1]), "r"(a[2]), "r"(a[3]), "r"(b[0]), "r"(b[1]));
}

// ---------------- prep ----------------
__global__ void prep_kernel(const float* __restrict__ Wh, const float* __restrict__ bh,
                            const float* __restrict__ Wo, const float* __restrict__ bo,
                            const float* __restrict__ h0) {
    int i = blockIdx.x * blockDim.x + threadIdx.x;
    if (i < 524288) {                      // Wo [1024][512] -> Wot [n][k]
        int k = i >> 9, n = i & 511;
        g_Wot[n * 1024 + k] = rna_tf32(Wo[i]);
    }
    if (i < 262144) {                      // Wh rows 0..511 / 512..1023
        int k = i >> 9, n = i & 511;
        g_W1t[n * 512 + k] = rna_tf32(Wh[i]);
        float w = Wh[262144 + i];
        g_Whh[i] = w;
        g_Wht[n * 512 + k] = rna_tf32(w);
    }
    if (i < 131072) g_Hall[i] = h0[i];
    if (i < 512) { g_bh[i] = bh[i]; g_bo[i] = bo[i]; }
}

// ---------------- fp32 512^3 GEMM for matrix squarings ----------------
__global__ __launch_bounds__(256) void sq512(const float* __restrict__ A,
                                             const float* __restrict__ B,
                                             float* __restrict__ C) {
    __shared__ float As[16][68];
    __shared__ float Bs[16][64];
    const int tid = threadIdx.x;
    const int bm = blockIdx.y * 64, bn = blockIdx.x * 64;
    const int tx = tid & 15, ty = tid >> 4;
    const int ar = tid >> 2, ac4 = (tid & 3) * 4;
    const int br = tid >> 4, bc4 = (tid & 15) * 4;

    float acc[4][4];
#pragma unroll
    for (int i = 0; i < 4; i++)
#pragma unroll
        for (int j = 0; j < 4; j++) acc[i][j] = 0.f;

    for (int k0 = 0; k0 < 512; k0 += 16) {
        float4 va = *(const float4*)(A + (size_t)(bm + ar) * 512 + k0 + ac4);
        float4 vb = *(const float4*)(B + (size_t)(k0 + br) * 512 + bn + bc4);
        __syncthreads();
        As[ac4 + 0][ar] = va.x; As[ac4 + 1][ar] = va.y;
        As[ac4 + 2][ar] = va.z; As[ac4 + 3][ar] = va.w;
        *(float4*)(&Bs[br][bc4]) = vb;
        __syncthreads();
#pragma unroll
        for (int kk = 0; kk < 16; kk++) {
            float a[4], b[4];
#pragma unroll
            for (int i = 0; i < 4; i++) a[i] = As[kk][ty * 4 + i];
#pragma unroll
            for (int j = 0; j < 4; j++) b[j] = Bs[kk][tx * 4 + j];
#pragma unroll
            for (int i = 0; i < 4; i++)
#pragma unroll
                for (int j = 0; j < 4; j++) acc[i][j] += a[i] * b[j];
        }
    }
#pragma unroll
    for (int i = 0; i < 4; i++) {
        float4 v = {acc[i][0], acc[i][1], acc[i][2], acc[i][3]};
        *(float4*)(C + (size_t)(bm + ty * 4 + i) * 512 + bn + tx * 4) = v;
    }
}

// ---------------- tf32 mma GEMM ----------------
// C[omap(m)][n] = epi( A[amap(m)][:] @ Bt[n][:] )
// MODE 0: +bias               (K=512)  e.g. G1
// MODE 1: sigmoid(+bias), A = concat(x | Hall-gathered) (K=1024)  G2
// MODE 2: +Add[addmap(m)][n]  (K=512)  Horner / recovery
template <int MODE>
__global__ __launch_bounds__(256) void mma_gemm(
    const float* __restrict__ A0, const float* __restrict__ A1, int amap, int aoff,
    const float* __restrict__ Add, int addmap, int addoff,
    float* __restrict__ O, int omap, int ooff,
    const float* __restrict__ Bt, const float* __restrict__ bias) {
    __shared__ float As[2][128][20];
    __shared__ float Bs[2][64][20];

    const int tid = threadIdx.x;
    const int lane = tid & 31;
    const int wid = tid >> 5;
    const int wm = (wid >> 1) * 32;    // 4 warps over M
    const int wn = (wid & 1) * 32;     // 2 warps over N
    const int bm = blockIdx.y * 128;
    const int bn = blockIdx.x * 64;
    const int KD = (MODE == 1) ? 1024 : 512;
    const int NIT = KD / 16;

    const int ar1 = tid >> 2, ac = (tid & 3) * 4;  // A: rows ar1, ar1+64
    const int br = tid >> 2, bc = (tid & 3) * 4;   // B: row br

    auto issue = [&](int it) {
        const int k0 = it * 16;
        const int buf = it & 1;
#pragma unroll
        for (int h = 0; h < 2; h++) {
            int gm = bm + ar1 + h * 64;
            const float* src;
            if (MODE == 1) {
                if (k0 < 512) src = A0 + (size_t)gm * 512 + k0 + ac;
                else src = A1 + (size_t)((((gm & 255) << 8) | (gm >> 8))) * 512 + (k0 - 512) + ac;
            } else {
                src = A0 + (size_t)rowmap(amap, aoff, gm) * 512 + k0 + ac;
            }
            uint32_t d = smem_u32(&As[buf][ar1 + h * 64][ac]);
            asm volatile("cp.async.cg.shared.global [%0], [%1], 16;" :: "r"(d), "l"(src));
        }
        const float* bsrc = Bt + (size_t)(bn + br) * KD + k0 + bc;
        uint32_t db = smem_u32(&Bs[buf][br][bc]);
        asm volatile("cp.async.cg.shared.global [%0], [%1], 16;" :: "r"(db), "l"(bsrc));
        asm volatile("cp.async.commit_group;");
    };

    float acc[2][4][4];
#pragma unroll
    for (int a = 0; a < 2; a++)
#pragma unroll
        for (int b = 0; b < 4; b++)
#pragma unroll
            for (int c = 0; c < 4; c++) acc[a][b][c] = 0.f;

    issue(0);
    for (int it = 0; it < NIT; it++) {
        if (it + 1 < NIT) {
            issue(it + 1);
            asm volatile("cp.async.wait_group 1;");
        } else {
            asm volatile("cp.async.wait_group 0;");
        }
        __syncthreads();
        const float(*Asb)[20] = As[it & 1];
        const float(*Bsb)[20] = Bs[it & 1];
#pragma unroll
        for (int kk = 0; kk < 2; kk++) {
            uint32_t af[2][4], bf[4][2];
            const int k = kk * 8 + (lane & 3);
#pragma unroll
            for (int mf = 0; mf < 2; mf++) {
                int r = wm + mf * 16 + (lane >> 2);
                af[mf][0] = rna_u(Asb[r][k]);
                af[mf][1] = rna_u(Asb[r + 8][k]);
                af[mf][2] = rna_u(Asb[r][k + 4]);
                af[mf][3] = rna_u(Asb[r + 8][k + 4]);
            }
#pragma unroll
            for (int nf = 0; nf < 4; nf++) {
                int r = wn + nf * 8 + (lane >> 2);
                bf[nf][0] = __float_as_uint(Bsb[r][k]);
                bf[nf][1] = __float_as_uint(Bsb[r][k + 4]);
            }
#pragma unroll
            for (int mf = 0; mf < 2; mf++)
#pragma unroll
                for (int nf = 0; nf < 4; nf++) mma8(acc[mf][nf], af[mf], bf[nf]);
        }
        __syncthreads();
    }

    // epilogue
#pragma unroll
    for (int mf = 0; mf < 2; mf++)
#pragma unroll
        for (int nf = 0; nf < 4; nf++) {
            int col = bn + wn + nf * 8 + (lane & 3) * 2;
#pragma unroll
            for (int h = 0; h < 2; h++) {
                int r = bm + wm + mf * 16 + (lane >> 2) + h * 8;
                float c0 = acc[mf][nf][h * 2 + 0];
                float c1 = acc[mf][nf][h * 2 + 1];
                if (MODE == 2) {
                    const float* ap = Add + (size_t)rowmap(addmap, addoff, r) * 512 + col;
                    c0 += ap[0]; c1 += ap[1];
                } else {
                    c0 += bias[col]; c1 += bias[col + 1];
                    if (MODE == 1) {
                        c0 = 1.f / (1.f + __expf(-c0));
                        c1 = 1.f / (1.f + __expf(-c1));
                    }
                }
                float2 v = {c0, c1};
                *(float2*)(O + (size_t)rowmap(omap, ooff, r) * 512 + col) = v;
            }
        }
}

// ---------------- sequential scan step (fp32, exact) ----------------
// Hall[4k+4] = Hall[4k] @ W4 + Q0[k]
__global__ __launch_bounds__(128) void step4_kernel(int k) {
    __shared__ float As[16][20];
    __shared__ float Bs[16][64];
    const float* __restrict__ hcur = g_Hall + (size_t)(4 * k) * 131072;
    float* __restrict__ hnext = g_Hall + (size_t)(4 * k + 4) * 131072;
    const float* __restrict__ add = g_Q0 + (size_t)k * 131072;

    const int bn = blockIdx.x * 64;
    const int bm = blockIdx.y * 16;
    const int tid = threadIdx.x;
    const int tx = tid & 15, ty = tid >> 4;
    const int arow = tid >> 3, acol = (tid & 7) * 2;
    const int brow = tid >> 4, bcol = (tid & 15) * 4;

    float acc[2][4] = {{0.f, 0.f, 0.f, 0.f}, {0.f, 0.f, 0.f, 0.f}};

    for (int k0 = 0; k0 < 512; k0 += 16) {
        float2 va = *(const float2*)(hcur + (size_t)(bm + arow) * 512 + k0 + acol);
        float4 vb0 = *(const float4*)(g_W4 + (size_t)(k0 + brow) * 512 + bn + bcol);
        float4 vb1 = *(const float4*)(g_W4 + (size_t)(k0 + brow + 8) * 512 + bn + bcol);
        As[acol + 0][arow] = va.x;
        As[acol + 1][arow] = va.y;
        *(float4*)(&Bs[brow][bcol]) = vb0;
        *(float4*)(&Bs[brow + 8][bcol]) = vb1;
        __syncthreads();
#pragma unroll
        for (int kk = 0; kk < 16; kk++) {
            float a0 = As[kk][ty * 2 + 0], a1 = As[kk][ty * 2 + 1];
            float b0 = Bs[kk][tx * 4 + 0], b1 = Bs[kk][tx * 4 + 1];
            float b2 = Bs[kk][tx * 4 + 2], b3 = Bs[kk][tx * 4 + 3];
            acc[0][0] += a0 * b0; acc[0][1] += a0 * b1;
            acc[0][2] += a0 * b2; acc[0][3] += a0 * b3;
            acc[1][0] += a1 * b0; acc[1][1] += a1 * b1;
            acc[1][2] += a1 * b2; acc[1][3] += a1 * b3;
        }
        __syncthreads();
    }
#pragma unroll
    for (int i = 0; i < 2; i++) {
        int m = bm + ty * 2 + i, n = bn + tx * 4;
        float4 p = *(const float4*)(add + (size_t)m * 512 + n);
        float4 v = {acc[i][0] + p.x, acc[i][1] + p.y, acc[i][2] + p.z, acc[i][3] + p.w};
        *(float4*)(hnext + (size_t)m * 512 + n) = v;
    }
}

__global__ void final_kernel(float* __restrict__ out) {
    int i = blockIdx.x * blockDim.x + threadIdx.x;
    if (i < 131072) out[(size_t)33554432 + i] = g_Hall[(size_t)33554432 + i];
}

// ---------------- launch ----------------
extern "C" void kernel_launch(void* const* d_in, const int* in_sizes, int n_in,
                              void* d_out, int out_size) {
    const float* x  = (const float*)d_in[0];
    const float* h0 = (const float*)d_in[1];
    const float* Wh = (const float*)d_in[2];
    const float* bh = (const float*)d_in[3];
    const float* Wo = (const float*)d_in[4];
    const float* bo = (const float*)d_in[5];
    float* out = (float*)d_out;

    float *preh, *hall, *q0, *q1, *w1t, *wht, *whh, *w2, *w4, *wot, *bhp, *bop;
    cudaGetSymbolAddress((void**)&preh, g_preh);
    cudaGetSymbolAddress((void**)&hall, g_Hall);
    cudaGetSymbolAddress((void**)&q0, g_Q0);
    cudaGetSymbolAddress((void**)&q1, g_Q1);
    cudaGetSymbolAddress((void**)&w1t, g_W1t);
    cudaGetSymbolAddress((void**)&wht, g_Wht);
    cudaGetSymbolAddress((void**)&whh, g_Whh);
    cudaGetSymbolAddress((void**)&w2, g_W2);
    cudaGetSymbolAddress((void**)&w4, g_W4);
    cudaGetSymbolAddress((void**)&wot, g_Wot);
    cudaGetSymbolAddress((void**)&bhp, g_bh);
    cudaGetSymbolAddress((void**)&bop, g_bo);

    prep_kernel<<<2048, 256>>>(Wh, bh, Wo, bo, h0);
    sq512<<<dim3(8, 8), 256>>>(whh, whh, w2);
    sq512<<<dim3(8, 8), 256>>>(w2, w2, w4);

    // G1: preh[t*256+b] = x[b][t] @ W_hx + b_h
    mma_gemm<0><<<dim3(8, 512), 256>>>(x, nullptr, 1, 0, nullptr, 0, 0,
                                       preh, 0, 0, w1t, bhp);
    // Horner: P[k] = ((preh[4k]@W + preh[4k+1])@W + preh[4k+2])@W + preh[4k+3]
    mma_gemm<2><<<dim3(8, 128), 256>>>(preh, nullptr, 2, 0, preh, 2, 1, q0, 0, 0, wht, nullptr);
    mma_gemm<2><<<dim3(8, 128), 256>>>(q0, nullptr, 0, 0, preh, 2, 2, q1, 0, 0, wht, nullptr);
    mma_gemm<2><<<dim3(8, 128), 256>>>(q1, nullptr, 0, 0, preh, 2, 3, q0, 0, 0, wht, nullptr);
    // sequential scan over 64 chunks
    for (int k = 0; k < 64; k++) step4_kernel<<<dim3(8, 16), 128>>>(k);
    // interior recovery: Hall[4k+i] = Hall[4k+i-1]@W + preh[4k+i-1]
    for (int i = 1; i <= 3; i++)
        mma_gemm<2><<<dim3(8, 128), 256>>>(hall, nullptr, 2, i - 1, preh, 2, i - 1,
                                           hall, 2, i, wht, nullptr);
    // G2: out[b*256+t] = sigmoid([x | Hall[t]] @ W_o + b_o)
    mma_gemm<1><<<dim3(8, 512), 256>>>(x, hall, 0, 0, nullptr, 0, 0,
                                       out, 0, 0, wot, bop);
    final_kernel<<<512, 256>>>(out);
}

// round 5
// speedup vs baseline: 3.1599x; 1.0962x over previous
#include <cuda_runtime.h>
#include <cstdint>

// ---------------- device-global scratch ----------------
__device__ float g_W1t[512 * 512];     // W_hx^T [n][k] tf32
__device__ float g_Wht[512 * 512];     // W_hh^T [n][k] tf32
__device__ float g_Whh[512 * 512];     // W_hh   fp32
__device__ float g_W2[512 * 512];      // W^2 fp32
__device__ float g_W4[512 * 512];      // W^4 fp32
__device__ float g_W4t[512 * 512];     // W^4^T tf32
__device__ float g_W8[512 * 512];      // W^8 fp32
__device__ float g_Wot[512 * 1024];    // W_o^T [n][k] tf32
__device__ float g_bh[512];
__device__ float g_bo[512];
__device__ float g_xr[(size_t)65536 * 512];        // tf32-rounded x [b*256+t][k]
__device__ float g_preh[(size_t)65536 * 512];      // [t*256+b][n] tf32-rounded
__device__ float g_Hall[(size_t)257 * 131072];     // [t][b][n] tf32-rounded
__device__ float g_hwork[2][131072];               // fp32 backbone ping-pong
__device__ float g_Q0[(size_t)16384 * 512];
__device__ float g_Q1[(size_t)16384 * 512];
__device__ int g_cnt, g_phase;

// ---------------- helpers ----------------
__device__ __forceinline__ uint32_t smem_u32(const void* p) {
    uint32_t a;
    asm("{ .reg .u64 t; cvta.to.shared.u64 t, %1; cvt.u32.u64 %0, t; }" : "=r"(a) : "l"(p));
    return a;
}
__device__ __forceinline__ float rna_tf32(float x) {
    uint32_t r; asm("cvt.rna.tf32.f32 %0, %1;" : "=r"(r) : "f"(x));
    return __uint_as_float(r);
}
// row maps: 0 id, 1 (b,t)swap, 2 chunk4 off, 3 chunk2 off
__device__ __forceinline__ int rowmap(int mode, int off, int m) {
    if (mode == 1) return ((m & 255) << 8) | (m >> 8);
    if (mode == 2) return ((m >> 8) << 10) + (off << 8) + (m & 255);
    if (mode == 3) return ((m >> 8) << 9) + (off << 8) + (m & 255);
    return m;
}
__device__ __forceinline__ void mma8(float* c, const uint32_t* a, const uint32_t* b) {
    asm volatile("mma.sync.aligned.m16n8k8.row.col.f32.tf32.tf32.f32 "
        "{%0,%1,%2,%3}, {%4,%5,%6,%7}, {%8,%9}, {%0,%1,%2,%3};"
        : "+f"(c[0]), "+f"(c[1]), "+f"(c[2]), "+f"(c[3])
        : "r"(a[0]), "r"(a[1]), "r"(a[2]), "r"(a[3]), "r"(b[0]), "r"(b[1]));
}

// ---------------- prep ----------------
__global__ void prep_kernel(const float* __restrict__ Wh, const float* __restrict__ bh,
                            const float* __restrict__ Wo, const float* __restrict__ bo,
                            const float* __restrict__ h0) {
    int i = blockIdx.x * blockDim.x + threadIdx.x;
    if (i == 0) { g_cnt = 0; g_phase = 0; }
    if (i < 524288) {
        int k = i >> 9, n = i & 511;
        g_Wot[n * 1024 + k] = rna_tf32(Wo[i]);
    }
    if (i < 262144) {
        int k = i >> 9, n = i & 511;
        g_W1t[n * 512 + k] = rna_tf32(Wh[i]);
        float w = Wh[262144 + i];
        g_Whh[i] = w;
        g_Wht[n * 512 + k] = rna_tf32(w);
    }
    if (i < 131072) {
        float h = h0[i];
        g_hwork[0][i] = h;
        g_Hall[i] = rna_tf32(h);
    }
    if (i < 512) { g_bh[i] = bh[i]; g_bo[i] = bo[i]; }
}

// round x (float4 per thread)
__global__ void xr_kernel(const float* __restrict__ x) {
    size_t i = ((size_t)blockIdx.x * blockDim.x + threadIdx.x) * 4;
    float4 v = *(const float4*)(x + i);
    v.x = rna_tf32(v.x); v.y = rna_tf32(v.y);
    v.z = rna_tf32(v.z); v.w = rna_tf32(v.w);
    *(float4*)(g_xr + i) = v;
}

// ---------------- fp32 512^3 GEMM (matrix squarings); Ct: rounded transpose ----------------
__global__ __launch_bounds__(256) void sq512(const float* __restrict__ A,
                                             const float* __restrict__ B,
                                             float* __restrict__ C,
                                             float* __restrict__ Ct) {
    __shared__ float As[16][68];
    __shared__ float Bs[16][64];
    const int tid = threadIdx.x;
    const int bm = blockIdx.y * 64, bn = blockIdx.x * 64;
    const int tx = tid & 15, ty = tid >> 4;
    const int ar = tid >> 2, ac4 = (tid & 3) * 4;
    const int br = tid >> 4, bc4 = (tid & 15) * 4;

    float acc[4][4];
#pragma unroll
    for (int i = 0; i < 4; i++)
#pragma unroll
        for (int j = 0; j < 4; j++) acc[i][j] = 0.f;

    for (int k0 = 0; k0 < 512; k0 += 16) {
        float4 va = *(const float4*)(A + (size_t)(bm + ar) * 512 + k0 + ac4);
        float4 vb = *(const float4*)(B + (size_t)(k0 + br) * 512 + bn + bc4);
        __syncthreads();
        As[ac4 + 0][ar] = va.x; As[ac4 + 1][ar] = va.y;
        As[ac4 + 2][ar] = va.z; As[ac4 + 3][ar] = va.w;
        *(float4*)(&Bs[br][bc4]) = vb;
        __syncthreads();
#pragma unroll
        for (int kk = 0; kk < 16; kk++) {
            float a[4], b[4];
#pragma unroll
            for (int i = 0; i < 4; i++) a[i] = As[kk][ty * 4 + i];
#pragma unroll
            for (int j = 0; j < 4; j++) b[j] = Bs[kk][tx * 4 + j];
#pragma unroll
            for (int i = 0; i < 4; i++)
#pragma unroll
                for (int j = 0; j < 4; j++) acc[i][j] += a[i] * b[j];
        }
    }
#pragma unroll
    for (int i = 0; i < 4; i++) {
        int m = bm + ty * 4 + i;
        float4 v = {acc[i][0], acc[i][1], acc[i][2], acc[i][3]};
        *(float4*)(C + (size_t)m * 512 + bn + tx * 4) = v;
        if (Ct) {
#pragma unroll
            for (int j = 0; j < 4; j++)
                Ct[(size_t)(bn + tx * 4 + j) * 512 + m] = rna_tf32(acc[i][j]);
        }
    }
}

// ---------------- tf32 mma GEMM (all operands pre-rounded; no in-loop cvt) ----------
// MODE 0: O = rna(A@Bt + bias)           K=512
// MODE 1: O = sigmoid(A@Bt + bias), A = [xr | Hall-gathered], K=1024
// MODE 2: O = rna(A@Bt + Add)            K=512
template <int MODE>
__global__ __launch_bounds__(256, 4) void mma_gemm(
    const float* __restrict__ A0, const float* __restrict__ A1, int amap, int aoff,
    const float* __restrict__ Add, int addmap, int addoff,
    float* __restrict__ O, int omap, int ooff,
    const float* __restrict__ Bt, const float* __restrict__ bias) {
    __shared__ float As[2][128][20];
    __shared__ float Bs[2][64][20];

    const int tid = threadIdx.x;
    const int lane = tid & 31;
    const int wid = tid >> 5;
    const int wm = (wid >> 1) * 32;
    const int wn = (wid & 1) * 32;
    const int bm = blockIdx.y * 128;
    const int bn = blockIdx.x * 64;
    const int KD = (MODE == 1) ? 1024 : 512;
    const int NIT = KD / 16;

    const int ar1 = tid >> 2, ac = (tid & 3) * 4;
    const int br = tid >> 2, bc = (tid & 3) * 4;

    // hoisted per-thread source pointers
    const float* aP[2];
    const float* aH[2];
#pragma unroll
    for (int h = 0; h < 2; h++) {
        int gm = bm + ar1 + h * 64;
        if (MODE == 1) {
            aP[h] = A0 + (size_t)gm * 512 + ac;
            aH[h] = A1 + (size_t)((((gm & 255) << 8) | (gm >> 8))) * 512 + ac;
        } else {
            aP[h] = A0 + (size_t)rowmap(amap, aoff, gm) * 512 + ac;
        }
    }
    const float* bP = Bt + (size_t)(bn + br) * KD + bc;

    auto issue = [&](int it) {
        const int k0 = it * 16;
        const int buf = it & 1;
#pragma unroll
        for (int h = 0; h < 2; h++) {
            const float* src = (MODE == 1 && k0 >= 512) ? aH[h] + (k0 - 512) : aP[h] + k0;
            uint32_t d = smem_u32(&As[buf][ar1 + h * 64][ac]);
            asm volatile("cp.async.cg.shared.global [%0], [%1], 16;" :: "r"(d), "l"(src));
        }
        uint32_t db = smem_u32(&Bs[buf][br][bc]);
        asm volatile("cp.async.cg.shared.global [%0], [%1], 16;" :: "r"(db), "l"(bP + k0));
        asm volatile("cp.async.commit_group;");
    };

    float acc[2][4][4];
#pragma unroll
    for (int a = 0; a < 2; a++)
#pragma unroll
        for (int b = 0; b < 4; b++)
#pragma unroll
            for (int c = 0; c < 4; c++) acc[a][b][c] = 0.f;

    issue(0);
    for (int it = 0; it < NIT; it++) {
        if (it + 1 < NIT) {
            issue(it + 1);
            asm volatile("cp.async.wait_group 1;");
        } else {
            asm volatile("cp.async.wait_group 0;");
        }
        __syncthreads();
        const float(*Asb)[20] = As[it & 1];
        const float(*Bsb)[20] = Bs[it & 1];
#pragma unroll
        for (int kk = 0; kk < 2; kk++) {
            uint32_t af[2][4], bf[4][2];
            const int k = kk * 8 + (lane & 3);
#pragma unroll
            for (int mf = 0; mf < 2; mf++) {
                int r = wm + mf * 16 + (lane >> 2);
                af[mf][0] = __float_as_uint(Asb[r][k]);
                af[mf][1] = __float_as_uint(Asb[r + 8][k]);
                af[mf][2] = __float_as_uint(Asb[r][k + 4]);
                af[mf][3] = __float_as_uint(Asb[r + 8][k + 4]);
            }
#pragma unroll
            for (int nf = 0; nf < 4; nf++) {
                int r = wn + nf * 8 + (lane >> 2);
                bf[nf][0] = __float_as_uint(Bsb[r][k]);
                bf[nf][1] = __float_as_uint(Bsb[r][k + 4]);
            }
#pragma unroll
            for (int mf = 0; mf < 2; mf++)
#pragma unroll
                for (int nf = 0; nf < 4; nf++) mma8(acc[mf][nf], af[mf], bf[nf]);
        }
        __syncthreads();
    }

#pragma unroll
    for (int mf = 0; mf < 2; mf++)
#pragma unroll
        for (int nf = 0; nf < 4; nf++) {
            int col = bn + wn + nf * 8 + (lane & 3) * 2;
#pragma unroll
            for (int h = 0; h < 2; h++) {
                int r = bm + wm + mf * 16 + (lane >> 2) + h * 8;
                float c0 = acc[mf][nf][h * 2 + 0];
                float c1 = acc[mf][nf][h * 2 + 1];
                float2 v;
                if (MODE == 2) {
                    const float* ap = Add + (size_t)rowmap(addmap, addoff, r) * 512 + col;
                    v.x = rna_tf32(c0 + ap[0]);
                    v.y = rna_tf32(c1 + ap[1]);
                } else if (MODE == 0) {
                    v.x = rna_tf32(c0 + bias[col]);
                    v.y = rna_tf32(c1 + bias[col + 1]);
                } else {
                    v.x = 1.f / (1.f + __expf(-(c0 + bias[col])));
                    v.y = 1.f / (1.f + __expf(-(c1 + bias[col + 1])));
                }
                *(float2*)(O + (size_t)rowmap(omap, ooff, r) * 512 + col) = v;
            }
        }
}

// ---------------- persistent sequential scan (fp32 backbone, 32 super-steps) -----
// per step k: h84 = h8k@W4 + Q4[2k] -> Hall[8k+4] (rounded)
//             h88 = h8k@W8 + Q8[k]  -> hwork[(k+1)&1] (fp32) + Hall[8k+8] (rounded)
__device__ __forceinline__ void gbar(int target) {
    __syncthreads();
    if (threadIdx.x == 0) {
        __threadfence();
        int old = atomicAdd(&g_cnt, 1);
        if (old == 127) {
            g_cnt = 0;
            __threadfence();
            atomicExch(&g_phase, target);
        } else {
            while (atomicAdd(&g_phase, 0) < target) {}
        }
    }
    __syncthreads();
}

__global__ __launch_bounds__(128) void scan_kernel(const float* __restrict__ q4,
                                                   const float* __restrict__ q8) {
    __shared__ float As[16][20];
    __shared__ float B4[16][64];
    __shared__ float B8[16][64];
    const int bn = blockIdx.x * 64;
    const int bm = blockIdx.y * 16;
    const int tid = threadIdx.x;
    const int tx = tid & 15, ty = tid >> 4;
    const int arow = tid >> 3, acol = (tid & 7) * 2;
    const int brow = tid >> 4, bcol = (tid & 15) * 4;

    for (int k = 0; k < 32; k++) {
        const float* hsrc = g_hwork[k & 1];
        float* hdst = g_hwork[(k + 1) & 1];
        float acc4[2][4] = {{0, 0, 0, 0}, {0, 0, 0, 0}};
        float acc8[2][4] = {{0, 0, 0, 0}, {0, 0, 0, 0}};

        for (int k0 = 0; k0 < 512; k0 += 16) {
            float2 va = __ldcg((const float2*)(hsrc + (size_t)(bm + arow) * 512 + k0 + acol));
            float4 v40 = *(const float4*)(g_W4 + (size_t)(k0 + brow) * 512 + bn + bcol);
            float4 v41 = *(const float4*)(g_W4 + (size_t)(k0 + brow + 8) * 512 + bn + bcol);
            float4 v80 = *(const float4*)(g_W8 + (size_t)(k0 + brow) * 512 + bn + bcol);
            float4 v81 = *(const float4*)(g_W8 + (size_t)(k0 + brow + 8) * 512 + bn + bcol);
            __syncthreads();
            As[acol + 0][arow] = va.x;
            As[acol + 1][arow] = va.y;
            *(float4*)(&B4[brow][bcol]) = v40;
            *(float4*)(&B4[brow + 8][bcol]) = v41;
            *(float4*)(&B8[brow][bcol]) = v80;
            *(float4*)(&B8[brow + 8][bcol]) = v81;
            __syncthreads();
#pragma unroll
            for (int kk = 0; kk < 16; kk++) {
                float a0 = As[kk][ty * 2 + 0], a1 = As[kk][ty * 2 + 1];
#pragma unroll
                for (int j = 0; j < 4; j++) {
                    float b4 = B4[kk][tx * 4 + j];
                    float b8 = B8[kk][tx * 4 + j];
                    acc4[0][j] += a0 * b4; acc4[1][j] += a1 * b4;
                    acc8[0][j] += a0 * b8; acc8[1][j] += a1 * b8;
                }
            }
        }

#pragma unroll
        for (int i = 0; i < 2; i++) {
            int m = bm + ty * 2 + i, n = bn + tx * 4;
            size_t off = (size_t)m * 512 + n;
            float4 p4 = __ldcg((const float4*)(q4 + (size_t)(2 * k) * 131072 + off));
            float4 o4 = {rna_tf32(acc4[i][0] + p4.x), rna_tf32(acc4[i][1] + p4.y),
                         rna_tf32(acc4[i][2] + p4.z), rna_tf32(acc4[i][3] + p4.w)};
            *(float4*)(g_Hall + (size_t)(8 * k + 4) * 131072 + off) = o4;

            float4 p8 = __ldcg((const float4*)(q8 + (size_t)k * 131072 + off));
            float4 v8 = {acc8[i][0] + p8.x, acc8[i][1] + p8.y,
                         acc8[i][2] + p8.z, acc8[i][3] + p8.w};
            *(float4*)(hdst + off) = v8;
            float4 o8 = {rna_tf32(v8.x), rna_tf32(v8.y), rna_tf32(v8.z), rna_tf32(v8.w)};
            *(float4*)(g_Hall + (size_t)(8 * k + 8) * 131072 + off) = o8;
        }
        gbar(k + 1);
    }
}

// h_final (exact fp32 backbone) -> tail of d_out
__global__ void final_kernel(float* __restrict__ out) {
    int i = blockIdx.x * blockDim.x + threadIdx.x;
    if (i < 131072) out[(size_t)33554432 + i] = g_hwork[0][i];
}

// ---------------- launch ----------------
extern "C" void kernel_launch(void* const* d_in, const int* in_sizes, int n_in,
                              void* d_out, int out_size) {
    const float* x  = (const float*)d_in[0];
    const float* h0 = (const float*)d_in[1];
    const float* Wh = (const float*)d_in[2];
    const float* bh = (const float*)d_in[3];
    const float* Wo = (const float*)d_in[4];
    const float* bo = (const float*)d_in[5];
    float* out = (float*)d_out;

    float *xr, *preh, *hall, *q0, *q1, *w1t, *wht, *whh, *w2, *w4, *w4t, *w8, *wot, *bhp, *bop;
    cudaGetSymbolAddress((void**)&xr, g_xr);
    cudaGetSymbolAddress((void**)&preh, g_preh);
    cudaGetSymbolAddress((void**)&hall, g_Hall);
    cudaGetSymbolAddress((void**)&q0, g_Q0);
    cudaGetSymbolAddress((void**)&q1, g_Q1);
    cudaGetSymbolAddress((void**)&w1t, g_W1t);
    cudaGetSymbolAddress((void**)&wht, g_Wht);
    cudaGetSymbolAddress((void**)&whh, g_Whh);
    cudaGetSymbolAddress((void**)&w2, g_W2);
    cudaGetSymbolAddress((void**)&w4, g_W4);
    cudaGetSymbolAddress((void**)&w4t, g_W4t);
    cudaGetSymbolAddress((void**)&w8, g_W8);
    cudaGetSymbolAddress((void**)&wot, g_Wot);
    cudaGetSymbolAddress((void**)&bhp, g_bh);
    cudaGetSymbolAddress((void**)&bop, g_bo);

    prep_kernel<<<2048, 256>>>(Wh, bh, Wo, bo, h0);
    xr_kernel<<<32768, 256>>>(x);
    sq512<<<dim3(8, 8), 256>>>(whh, whh, w2, nullptr);
    sq512<<<dim3(8, 8), 256>>>(w2, w2, w4, w4t);
    sq512<<<dim3(8, 8), 256>>>(w4, w4, w8, nullptr);

    // G1: preh[t*256+b] = rna(xr[b][t] @ W_hx + b_h)
    mma_gemm<0><<<dim3(8, 512), 256>>>(xr, nullptr, 1, 0, nullptr, 0, 0,
                                       preh, 0, 0, w1t, bhp);
    // Horner over chunks of 4 -> Q4 in q0
    mma_gemm<2><<<dim3(8, 128), 256>>>(preh, nullptr, 2, 0, preh, 2, 1, q0, 0, 0, wht, nullptr);
    mma_gemm<2><<<dim3(8, 128), 256>>>(q0, nullptr, 0, 0, preh, 2, 2, q1, 0, 0, wht, nullptr);
    mma_gemm<2><<<dim3(8, 128), 256>>>(q1, nullptr, 0, 0, preh, 2, 3, q0, 0, 0, wht, nullptr);
    // Q8[k] = Q4[2k]@W4 + Q4[2k+1]  -> q1
    mma_gemm<2><<<dim3(8, 64), 256>>>(q0, nullptr, 3, 0, q0, 3, 1, q1, 0, 0, w4t, nullptr);
    // persistent sequential scan (32 super-steps)
    scan_kernel<<<dim3(8, 16), 128>>>(q0, q1);
    // interior recovery: Hall[4j+i] = rna(Hall[4j+i-1]@W + preh[4j+i-1])
    for (int i = 1; i <= 3; i++)
        mma_gemm<2><<<dim3(8, 128), 256>>>(hall, nullptr, 2, i - 1, preh, 2, i - 1,
                                           hall, 2, i, wht, nullptr);
    // G2: out[b*256+t] = sigmoid([xr | Hall[t]] @ W_o + b_o)
    mma_gemm<1><<<dim3(8, 512), 256>>>(xr, hall, 0, 0, nullptr, 0, 0,
                                       out, 0, 0, wot, bop);
    final_kernel<<<512, 256>>>(out);
}

// round 7
// speedup vs baseline: 3.7390x; 1.1833x over previous
#include <cuda_runtime.h>
#include <cstdint>

// ---------------- device-global scratch ----------------
__device__ float g_W1t[512 * 512];      // W_hx^T [n][k] tf32
__device__ float g_Wht[512 * 512];      // W_hh^T [n][k] tf32
__device__ float g_Whh[512 * 512];      // W_hh fp32
__device__ float g_W2[512 * 512];       // W^2 fp32
__device__ float g_W4[512 * 512];       // W^4 fp32
__device__ float g_W8[512 * 512];       // W^8 fp32
__device__ float g_WCt[1024 * 512];     // [W4t ; W8t] tf32 [n][k]
__device__ float g_Wot[512 * 1024];     // W_o^T [n][k] tf32
__device__ float g_bh[512];
__device__ float g_bo[512];
__device__ float g_xr[(size_t)65536 * 512];     // tf32-rounded x [b*256+t][k]
__device__ float g_preh[(size_t)65536 * 512];   // [t*256+b][n] tf32-rounded
__device__ float g_Hall[(size_t)257 * 131072];  // [t][b][n] tf32-rounded
__device__ float g_hfin[131072];                // fp32 h_final
__device__ float g_Q0[(size_t)16384 * 512];
__device__ float g_Q1[(size_t)16384 * 512];
__device__ int g_cnt, g_phase;

// ---------------- helpers ----------------
__device__ __forceinline__ uint32_t smem_u32(const void* p) {
    uint32_t a;
    asm("{ .reg .u64 t; cvta.to.shared.u64 t, %1; cvt.u32.u64 %0, t; }" : "=r"(a) : "l"(p));
    return a;
}
__device__ __forceinline__ float rna_tf32(float x) {
    uint32_t r; asm("cvt.rna.tf32.f32 %0, %1;" : "=r"(r) : "f"(x));
    return __uint_as_float(r);
}
__device__ __forceinline__ int rowmap(int mode, int off, int m) {
    if (mode == 1) return ((m & 255) << 8) | (m >> 8);
    if (mode == 2) return ((m >> 8) << 10) + (off << 8) + (m & 255);
    if (mode == 3) return ((m >> 8) << 9) + (off << 8) + (m & 255);
    return m;
}
__device__ __forceinline__ void mma8(float* c, const uint32_t* a, const uint32_t* b) {
    asm volatile("mma.sync.aligned.m16n8k8.row.col.f32.tf32.tf32.f32 "
        "{%0,%1,%2,%3}, {%4,%5,%6,%7}, {%8,%9}, {%0,%1,%2,%3};"
        : "+f"(c[0]), "+f"(c[1]), "+f"(c[2]), "+f"(c[3])
        : "r"(a[0]), "r"(a[1]), "r"(a[2]), "r"(a[3]), "r"(b[0]), "r"(b[1]));
}
#define CP16(dst, src) asm volatile("cp.async.cg.shared.global [%0], [%1], 16;" :: "r"(dst), "l"(src))

// ---------------- prep ----------------
__global__ void prep_kernel(const float* __restrict__ Wh, const float* __restrict__ bh,
                            const float* __restrict__ Wo, const float* __restrict__ bo,
                            const float* __restrict__ h0) {
    int i = blockIdx.x * blockDim.x + threadIdx.x;
    if (i == 0) { g_cnt = 0; g_phase = 0; }
    if (i < 524288) {
        int k = i >> 9, n = i & 511;
        g_Wot[n * 1024 + k] = rna_tf32(Wo[i]);
    }
    if (i < 262144) {
        int k = i >> 9, n = i & 511;
        g_W1t[n * 512 + k] = rna_tf32(Wh[i]);
        float w = Wh[262144 + i];
        g_Whh[i] = w;
        g_Wht[n * 512 + k] = rna_tf32(w);
    }
    if (i < 131072) g_Hall[i] = rna_tf32(h0[i]);
    if (i < 512) { g_bh[i] = bh[i]; g_bo[i] = bo[i]; }
}

__global__ void xr_kernel(const float* __restrict__ x) {
    size_t i = ((size_t)blockIdx.x * blockDim.x + threadIdx.x) * 4;
    float4 v = *(const float4*)(x + i);
    v.x = rna_tf32(v.x); v.y = rna_tf32(v.y);
    v.z = rna_tf32(v.z); v.w = rna_tf32(v.w);
    *(float4*)(g_xr + i) = v;
}

// ------------- fp32 512^3 GEMM (squarings), 32x64 tile, grid(8,16) -------------
__global__ __launch_bounds__(256) void sq512(const float* __restrict__ A,
                                             const float* __restrict__ B,
                                             float* __restrict__ C,
                                             float* __restrict__ Ct) {
    __shared__ float As[16][36];
    __shared__ float Bs[16][64];
    const int tid = threadIdx.x;
    const int bm = blockIdx.y * 32, bn = blockIdx.x * 64;
    const int tx = tid & 15, ty = tid >> 4;
    const int ar = tid >> 3, ac2 = (tid & 7) * 2;
    const int br = tid >> 4, bc4 = (tid & 15) * 4;

    float acc[2][4] = {{0, 0, 0, 0}, {0, 0, 0, 0}};
    for (int k0 = 0; k0 < 512; k0 += 16) {
        float2 va = *(const float2*)(A + (size_t)(bm + ar) * 512 + k0 + ac2);
        float4 vb = *(const float4*)(B + (size_t)(k0 + br) * 512 + bn + bc4);
        __syncthreads();
        As[ac2 + 0][ar] = va.x;
        As[ac2 + 1][ar] = va.y;
        *(float4*)(&Bs[br][bc4]) = vb;
        __syncthreads();
#pragma unroll
        for (int kk = 0; kk < 16; kk++) {
            float a0 = As[kk][ty * 2 + 0], a1 = As[kk][ty * 2 + 1];
#pragma unroll
            for (int j = 0; j < 4; j++) {
                float b = Bs[kk][tx * 4 + j];
                acc[0][j] += a0 * b;
                acc[1][j] += a1 * b;
            }
        }
    }
#pragma unroll
    for (int i = 0; i < 2; i++) {
        int m = bm + ty * 2 + i;
        float4 v = {acc[i][0], acc[i][1], acc[i][2], acc[i][3]};
        *(float4*)(C + (size_t)m * 512 + bn + tx * 4) = v;
        if (Ct) {
#pragma unroll
            for (int j = 0; j < 4; j++)
                Ct[(size_t)(bn + tx * 4 + j) * 512 + m] = rna_tf32(acc[i][j]);
        }
    }
}

// ---------------- tf32 mma GEMM, 128x128 tile ----------------
// MODE 0: O = rna(A@Bt + bias)  K=512 | MODE 1: sigmoid, A=[xr|Hall-gather], K=1024
// MODE 2: O = rna(A@Bt + Add)   K=512
template <int MODE>
__global__ __launch_bounds__(256, 2) void mma_gemm(
    const float* __restrict__ A0, const float* __restrict__ A1, int amap, int aoff,
    const float* __restrict__ Add, int addmap, int addoff,
    float* __restrict__ O, int omap, int ooff,
    const float* __restrict__ Bt, const float* __restrict__ bias) {
    __shared__ float As[2][128][20];
    __shared__ float Bs[2][128][20];

    const int tid = threadIdx.x;
    const int lane = tid & 31;
    const int wid = tid >> 5;
    const int wm = (wid >> 2) * 64;
    const int wn = (wid & 3) * 32;
    const int bm = blockIdx.y * 128;
    const int bn = blockIdx.x * 128;
    const int KD = (MODE == 1) ? 1024 : 512;
    const int NIT = KD / 16;

    const int ar1 = tid >> 2, ac = (tid & 3) * 4;

    const float* aP[2];
    const float* aH[2];
#pragma unroll
    for (int h = 0; h < 2; h++) {
        int gm = bm + ar1 + h * 64;
        if (MODE == 1) {
            aP[h] = A0 + (size_t)gm * 512 + ac;
            aH[h] = A1 + (size_t)((((gm & 255) << 8) | (gm >> 8))) * 512 + ac;
        } else {
            aP[h] = A0 + (size_t)rowmap(amap, aoff, gm) * 512 + ac;
        }
    }
    const float* bP = Bt + (size_t)(bn + ar1) * KD + ac;

    auto issue = [&](int it) {
        const int k0 = it * 16;
        const int buf = it & 1;
#pragma unroll
        for (int h = 0; h < 2; h++) {
            const float* src = (MODE == 1 && k0 >= 512) ? aH[h] + (k0 - 512) : aP[h] + k0;
            CP16(smem_u32(&As[buf][ar1 + h * 64][ac]), src);
            CP16(smem_u32(&Bs[buf][ar1 + h * 64][ac]), bP + (size_t)h * 64 * KD + k0);
        }
        asm volatile("cp.async.commit_group;");
    };

    float acc[4][4][4];
#pragma unroll
    for (int a = 0; a < 4; a++)
#pragma unroll
        for (int b = 0; b < 4; b++)
#pragma unroll
            for (int c = 0; c < 4; c++) acc[a][b][c] = 0.f;

    issue(0);
    for (int it = 0; it < NIT; it++) {
        if (it + 1 < NIT) {
            issue(it + 1);
            asm volatile("cp.async.wait_group 1;");
        } else {
            asm volatile("cp.async.wait_group 0;");
        }
        __syncthreads();
        const float(*Asb)[20] = As[it & 1];
        const float(*Bsb)[20] = Bs[it & 1];
#pragma unroll
        for (int kk = 0; kk < 2; kk++) {
            const int kf = kk * 8 + (lane & 3);
            uint32_t af[4][4], bf[4][2];
#pragma unroll
            for (int mf = 0; mf < 4; mf++) {
                int r = wm + mf * 16 + (lane >> 2);
                af[mf][0] = __float_as_uint(Asb[r][kf]);
                af[mf][1] = __float_as_uint(Asb[r + 8][kf]);
                af[mf][2] = __float_as_uint(Asb[r][kf + 4]);
                af[mf][3] = __float_as_uint(Asb[r + 8][kf + 4]);
            }
#pragma unroll
            for (int nf = 0; nf < 4; nf++) {
                int r = wn + nf * 8 + (lane >> 2);
                bf[nf][0] = __float_as_uint(Bsb[r][kf]);
                bf[nf][1] = __float_as_uint(Bsb[r][kf + 4]);
            }
#pragma unroll
            for (int mf = 0; mf < 4; mf++)
#pragma unroll
                for (int nf = 0; nf < 4; nf++) mma8(acc[mf][nf], af[mf], bf[nf]);
        }
        __syncthreads();
    }

#pragma unroll
    for (int mf = 0; mf < 4; mf++)
#pragma unroll
        for (int nf = 0; nf < 4; nf++) {
            int col = bn + wn + nf * 8 + (lane & 3) * 2;
#pragma unroll
            for (int h = 0; h < 2; h++) {
                int r = bm + wm + mf * 16 + (lane >> 2) + h * 8;
                float c0 = acc[mf][nf][h * 2 + 0];
                float c1 = acc[mf][nf][h * 2 + 1];
                float2 v;
                if (MODE == 2) {
                    const float* ap = Add + (size_t)rowmap(addmap, addoff, r) * 512 + col;
                    v.x = rna_tf32(c0 + ap[0]);
                    v.y = rna_tf32(c1 + ap[1]);
                } else if (MODE == 0) {
                    v.x = rna_tf32(c0 + bias[col]);
                    v.y = rna_tf32(c1 + bias[col + 1]);
                } else {
                    v.x = 1.f / (1.f + __expf(-(c0 + bias[col])));
                    v.y = 1.f / (1.f + __expf(-(c1 + bias[col + 1])));
                }
                *(float2*)(O + (size_t)rowmap(omap, ooff, r) * 512 + col) = v;
            }
        }
}

// ---------------- persistent tensor-core scan ----------------
// superstep k: C[256x1024] = Hall[8k] @ [W4t ; W8t]
//   left  half: Hall[8k+4] = rna(C_l + Q4[2k])
//   right half: Hall[8k+8] = rna(C_r + Q8[k]);  k==31 -> g_hfin fp32
__device__ __forceinline__ void gbar(int target) {
    __syncthreads();
    if (threadIdx.x == 0) {
        __threadfence();
        int old = atomicAdd(&g_cnt, 1);
        if (old == 63) {
            g_cnt = 0;
            __threadfence();
            atomicExch(&g_phase, target);
        } else {
            while (atomicAdd(&g_phase, 0) < target) {}
        }
    }
    __syncthreads();
}

__global__ __launch_bounds__(256) void scan_kernel(const float* __restrict__ q4,
                                                   const float* __restrict__ q8) {
    __shared__ float As[2][32][20];
    __shared__ float Bs[2][128][20];
    const int tid = threadIdx.x;
    const int lane = tid & 31;
    const int wid = tid >> 5;
    const int wm = (wid >> 2) * 16;
    const int wn = (wid & 3) * 32;
    const int bn = blockIdx.x * 128;    // over N=1024
    const int bm = blockIdx.y * 32;     // over M=256
    // A loaders: threads 0..127, 16B each (32 rows x 16 floats per buffer)
    const int aar = tid >> 2, aac = (tid & 3) * 4;
    const int br = tid >> 2, bc = (tid & 3) * 4;
    const float* bP = g_WCt + (size_t)(bn + br) * 512 + bc;

    for (int k = 0; k < 32; k++) {
        const float* hsrc = g_Hall + (size_t)(8 * k) * 131072;

        auto issue = [&](int it) {
            const int k0 = it * 16;
            const int buf = it & 1;
            if (tid < 128)
                CP16(smem_u32(&As[buf][aar][aac]), hsrc + (size_t)(bm + aar) * 512 + k0 + aac);
#pragma unroll
            for (int h = 0; h < 2; h++)
                CP16(smem_u32(&Bs[buf][br + h * 64][bc]), bP + (size_t)h * 64 * 512 + k0);
            asm volatile("cp.async.commit_group;");
        };

        float acc[4][4];
#pragma unroll
        for (int a = 0; a < 4; a++)
#pragma unroll
            for (int b = 0; b < 4; b++) acc[a][b] = 0.f;

        issue(0);
        for (int it = 0; it < 32; it++) {
            if (it + 1 < 32) {
                issue(it + 1);
                asm volatile("cp.async.wait_group 1;");
            } else {
                asm volatile("cp.async.wait_group 0;");
            }
            __syncthreads();
            const float(*Asb)[20] = As[it & 1];
            const float(*Bsb)[20] = Bs[it & 1];
#pragma unroll
            for (int kk = 0; kk < 2; kk++) {
                const int kf = kk * 8 + (lane & 3);
                uint32_t af[4], bf[4][2];
                int r = wm + (lane >> 2);
                af[0] = __float_as_uint(Asb[r][kf]);
                af[1] = __float_as_uint(Asb[r + 8][kf]);
                af[2] = __float_as_uint(Asb[r][kf + 4]);
                af[3] = __float_as_uint(Asb[r + 8][kf + 4]);
#pragma unroll
                for (int nf = 0; nf < 4; nf++) {
                    int rb = wn + nf * 8 + (lane >> 2);
                    bf[nf][0] = __float_as_uint(Bsb[rb][kf]);
                    bf[nf][1] = __float_as_uint(Bsb[rb][kf + 4]);
                }
#pragma unroll
                for (int nf = 0; nf < 4; nf++) mma8(acc[nf], af, bf[nf]);
            }
            __syncthreads();
        }

#pragma unroll
        for (int nf = 0; nf < 4; nf++) {
            int col = bn + wn + nf * 8 + (lane & 3) * 2;
#pragma unroll
            for (int h = 0; h < 2; h++) {
                int r = bm + wm + (lane >> 2) + h * 8;
                float c0 = acc[nf][h * 2 + 0];
                float c1 = acc[nf][h * 2 + 1];
                size_t off = (size_t)r * 512;
                if (bn < 512) {
                    const float* p = q4 + (size_t)(2 * k) * 131072 + off + col;
                    float2 v = {rna_tf32(c0 + p[0]), rna_tf32(c1 + p[1])};
                    *(float2*)(g_Hall + (size_t)(8 * k + 4) * 131072 + off + col) = v;
                } else {
                    int c2 = col - 512;
                    const float* p = q8 + (size_t)k * 131072 + off + c2;
                    float f0 = c0 + p[0], f1 = c1 + p[1];
                    float2 v = {rna_tf32(f0), rna_tf32(f1)};
                    *(float2*)(g_Hall + (size_t)(8 * k + 8) * 131072 + off + c2) = v;
                    if (k == 31) {
                        float2 w = {f0, f1};
                        *(float2*)(g_hfin + off + c2) = w;
                    }
                }
            }
        }
        gbar(k + 1);
    }
}

__global__ void final_kernel(float* __restrict__ out) {
    int i = blockIdx.x * blockDim.x + threadIdx.x;
    if (i < 131072) out[(size_t)33554432 + i] = g_hfin[i];
}

// ---------------- launch ----------------
extern "C" void kernel_launch(void* const* d_in, const int* in_sizes, int n_in,
                              void* d_out, int out_size) {
    const float* x  = (const float*)d_in[0];
    const float* h0 = (const float*)d_in[1];
    const float* Wh = (const float*)d_in[2];
    const float* bh = (const float*)d_in[3];
    const float* Wo = (const float*)d_in[4];
    const float* bo = (const float*)d_in[5];
    float* out = (float*)d_out;

    float *xr, *preh, *hall, *q0, *q1, *w1t, *wht, *whh, *w2, *w4, *w8, *wct, *wot, *bhp, *bop;
    cudaGetSymbolAddress((void**)&xr, g_xr);
    cudaGetSymbolAddress((void**)&preh, g_preh);
    cudaGetSymbolAddress((void**)&hall, g_Hall);
    cudaGetSymbolAddress((void**)&q0, g_Q0);
    cudaGetSymbolAddress((void**)&q1, g_Q1);
    cudaGetSymbolAddress((void**)&w1t, g_W1t);
    cudaGetSymbolAddress((void**)&wht, g_Wht);
    cudaGetSymbolAddress((void**)&whh, g_Whh);
    cudaGetSymbolAddress((void**)&w2, g_W2);
    cudaGetSymbolAddress((void**)&w4, g_W4);
    cudaGetSymbolAddress((void**)&w8, g_W8);
    cudaGetSymbolAddress((void**)&wct, g_WCt);
    cudaGetSymbolAddress((void**)&wot, g_Wot);
    cudaGetSymbolAddress((void**)&bhp, g_bh);
    cudaGetSymbolAddress((void**)&bop, g_bo);

    prep_kernel<<<2048, 256>>>(Wh, bh, Wo, bo, h0);
    xr_kernel<<<32768, 256>>>(x);
    sq512<<<dim3(8, 16), 256>>>(whh, whh, w2, nullptr);
    sq512<<<dim3(8, 16), 256>>>(w2, w2, w4, wct);             // W4 + W4t(tf32)
    sq512<<<dim3(8, 16), 256>>>(w4, w4, w8, wct + 262144);    // W8 + W8t(tf32)

    // G1: preh[t*256+b] = rna(xr[b][t] @ W_hx + b_h)
    mma_gemm<0><<<dim3(4, 512), 256>>>(xr, nullptr, 1, 0, nullptr, 0, 0,
                                       preh, 0, 0, w1t, bhp);
    // Horner chunks of 4 -> Q4 (q0)
    mma_gemm<2><<<dim3(4, 128), 256>>>(preh, nullptr, 2, 0, preh, 2, 1, q0, 0, 0, wht, nullptr);
    mma_gemm<2><<<dim3(4, 128), 256>>>(q0, nullptr, 0, 0, preh, 2, 2, q1, 0, 0, wht, nullptr);
    mma_gemm<2><<<dim3(4, 128), 256>>>(q1, nullptr, 0, 0, preh, 2, 3, q0, 0, 0, wht, nullptr);
    // Q8[k] = Q4[2k]@W4 + Q4[2k+1] -> q1  (W4t = first half of WCt)
    mma_gemm<2><<<dim3(4, 64), 256>>>(q0, nullptr, 3, 0, q0, 3, 1, q1, 0, 0, wct, nullptr);
    // persistent tensor-core scan, 32 supersteps
    scan_kernel<<<dim3(8, 8), 256>>>(q0, q1);
    // interior recovery: Hall[4j+i] = rna(Hall[4j+i-1]@W + preh[4j+i-1])
    for (int i = 1; i <= 3; i++)
        mma_gemm<2><<<dim3(4, 128), 256>>>(hall, nullptr, 2, i - 1, preh, 2, i - 1,
                                           hall, 2, i, wht, nullptr);
    // G2: out[b*256+t] = sigmoid([xr | Hall[t]] @ W_o + b_o)
    mma_gemm<1><<<dim3(4, 512), 256>>>(xr, hall, 0, 0, nullptr, 0, 0,
                                       out, 0, 0, wot, bop);
    final_kernel<<<512, 256>>>(out);
}